// round 3
// baseline (speedup 1.0000x reference)
#include <cuda_runtime.h>
#include <math.h>

#define N_ROWS 32768
#define DIM    256
#define KCODES 8192

// ---- scratch (device globals; no runtime allocation) ----
__device__ float  g_xnorm[N_ROWS];
__device__ float  g_enorm[KCODES];
__device__ int    g_bestIdx[N_ROWS];
__device__ float  g_embT[KCODES * DIM];     // E transposed: [K][D], 8MB
__device__ double g_partial[512];

// ---------------------------------------------------------------------------
// ||e_k||^2 for each code k. E is [D, K] row-major -> column k is strided,
// but across threads each d-iteration is fully coalesced.
// ---------------------------------------------------------------------------
__global__ void enorm_kernel(const float* __restrict__ E) {
    int k = blockIdx.x * blockDim.x + threadIdx.x;
    if (k >= KCODES) return;
    float s = 0.0f;
    #pragma unroll 8
    for (int d = 0; d < DIM; d++) {
        float v = E[d * KCODES + k];
        s += v * v;
    }
    g_enorm[k] = s;
}

// ---------------------------------------------------------------------------
// Transpose E [D,K] -> g_embT [K,D] so the final gather is coalesced.
// ---------------------------------------------------------------------------
__global__ void transpose_kernel(const float* __restrict__ E) {
    __shared__ float tile[32][33];
    int kBase = blockIdx.x * 32;
    int dBase = blockIdx.y * 32;
    int tx = threadIdx.x, ty = threadIdx.y;   // blockDim = (32, 8)
    #pragma unroll
    for (int i = 0; i < 32; i += 8)
        tile[ty + i][tx] = E[(dBase + ty + i) * KCODES + kBase + tx];
    __syncthreads();
    #pragma unroll
    for (int i = 0; i < 32; i += 8)
        g_embT[(kBase + ty + i) * DIM + dBase + tx] = tile[tx][ty + i];
}

// ---------------------------------------------------------------------------
// ||x_n||^2 per row: one warp per row, float4 loads, shfl reduce.
// ---------------------------------------------------------------------------
__global__ void xnorm_kernel(const float* __restrict__ X) {
    int gwarp = (blockIdx.x * blockDim.x + threadIdx.x) >> 5;
    int lane  = threadIdx.x & 31;
    if (gwarp >= N_ROWS) return;
    const float* xr = X + (size_t)gwarp * DIM;
    float s = 0.0f;
    #pragma unroll
    for (int i = 0; i < 2; i++) {
        float4 v = *(const float4*)&xr[lane * 8 + i * 4];
        s += v.x * v.x + v.y * v.y + v.z * v.z + v.w * v.w;
    }
    #pragma unroll
    for (int off = 16; off > 0; off >>= 1)
        s += __shfl_xor_sync(0xFFFFFFFFu, s, off);
    if (lane == 0) g_xnorm[gwarp] = s;
}

// ---------------------------------------------------------------------------
// Fused distance GEMM + running argmin.
// Block tile: 128 rows x 128 codes, 256 threads, 8x8 register tile,
// D processed in chunks of 32 (16KB + 16KB static smem).
// dist = (xnorm - 2*dot) + enorm, strict '<' keeps FIRST minimum (matches
// jnp.argmin tie-breaking) since k is scanned in ascending order per thread
// and the cross-thread reduction breaks value-ties by smaller index.
// ---------------------------------------------------------------------------
__global__ __launch_bounds__(256) void argmin_kernel(const float* __restrict__ X,
                                                     const float* __restrict__ E) {
    __shared__ float xs[32 * 128];   // [d][row]
    __shared__ float es[32 * 128];   // [d][k]

    int tid  = threadIdx.x;
    int tcol = tid & 15;             // 0..15  -> 8 codes each
    int trow = tid >> 4;             // 0..15  -> 8 rows each
    int rowBase = blockIdx.x * 128;

    float xn[8];
    #pragma unroll
    for (int i = 0; i < 8; i++) xn[i] = g_xnorm[rowBase + trow * 8 + i];

    float bv[8];
    int   bi[8];
    #pragma unroll
    for (int i = 0; i < 8; i++) { bv[i] = INFINITY; bi[i] = 0; }

    for (int kt = 0; kt < KCODES; kt += 128) {
        float acc[8][8];
        #pragma unroll
        for (int i = 0; i < 8; i++)
            #pragma unroll
            for (int j = 0; j < 8; j++) acc[i][j] = 0.0f;

        for (int dc = 0; dc < DIM; dc += 32) {
            __syncthreads();
            // Load X chunk [128 rows][32 d], store transposed xs[d][row]
            #pragma unroll
            for (int l = 0; l < 4; l++) {
                int f4 = tid + l * 256;        // 0..1023
                int r  = f4 >> 3;              // 8 float4 per row
                int d4 = f4 & 7;
                float4 v = *(const float4*)&X[(size_t)(rowBase + r) * DIM + dc + d4 * 4];
                xs[(d4 * 4 + 0) * 128 + r] = v.x;
                xs[(d4 * 4 + 1) * 128 + r] = v.y;
                xs[(d4 * 4 + 2) * 128 + r] = v.z;
                xs[(d4 * 4 + 3) * 128 + r] = v.w;
            }
            // Load E chunk [32 d][128 k] directly (already k-contiguous)
            #pragma unroll
            for (int l = 0; l < 4; l++) {
                int f4 = tid + l * 256;        // 0..1023
                int dd = f4 >> 5;              // 32 float4 per d-row
                int c4 = f4 & 31;
                *(float4*)&es[dd * 128 + c4 * 4] =
                    *(const float4*)&E[(size_t)(dc + dd) * KCODES + kt + c4 * 4];
            }
            __syncthreads();

            #pragma unroll 4
            for (int d = 0; d < 32; d++) {
                float a[8], b[8];
                *(float4*)(a)     = *(float4*)&xs[d * 128 + trow * 8];
                *(float4*)(a + 4) = *(float4*)&xs[d * 128 + trow * 8 + 4];
                *(float4*)(b)     = *(float4*)&es[d * 128 + tcol * 8];
                *(float4*)(b + 4) = *(float4*)&es[d * 128 + tcol * 8 + 4];
                #pragma unroll
                for (int i = 0; i < 8; i++)
                    #pragma unroll
                    for (int j = 0; j < 8; j++)
                        acc[i][j] += a[i] * b[j];
            }
        }

        // Epilogue: distances + running first-min (j ascending, tiles ascending)
        float en[8];
        #pragma unroll
        for (int j = 0; j < 8; j++) en[j] = g_enorm[kt + tcol * 8 + j];
        #pragma unroll
        for (int i = 0; i < 8; i++) {
            #pragma unroll
            for (int j = 0; j < 8; j++) {
                float dist = (xn[i] - 2.0f * acc[i][j]) + en[j];
                if (dist < bv[i]) { bv[i] = dist; bi[i] = kt + tcol * 8 + j; }
            }
        }
    }

    // Cross-thread reduction: 16 candidates per row, value-then-index order.
    __syncthreads();
    float* redV = xs;                 // [128][16]
    int*   redI = (int*)es;           // [128][16]
    #pragma unroll
    for (int i = 0; i < 8; i++) {
        redV[(trow * 8 + i) * 16 + tcol] = bv[i];
        redI[(trow * 8 + i) * 16 + tcol] = bi[i];
    }
    __syncthreads();
    if (tid < 128) {
        float best = INFINITY;
        int bidx = 0x7FFFFFFF;
        #pragma unroll
        for (int c = 0; c < 16; c++) {
            float v = redV[tid * 16 + c];
            int   ix = redI[tid * 16 + c];
            if (v < best || (v == best && ix < bidx)) { best = v; bidx = ix; }
        }
        g_bestIdx[rowBase + tid] = bidx;
    }
}

// ---------------------------------------------------------------------------
// Gather quantized vectors (coalesced via g_embT) + per-block loss partials.
// 512 blocks x 64 rows; deterministic per-thread then fixed-tree reduce.
// ---------------------------------------------------------------------------
__global__ __launch_bounds__(256) void gather_loss_kernel(const float* __restrict__ X,
                                                          float* __restrict__ out) {
    int base = blockIdx.x * 64;       // rows
    double lsum = 0.0;
    for (int e = threadIdx.x; e < 64 * 64; e += 256) {
        int r  = e >> 6;
        int d4 = e & 63;
        int row = base + r;
        int idx = g_bestIdx[row];
        float4 q = *(const float4*)&g_embT[(size_t)idx * DIM + d4 * 4];
        float4 x = *(const float4*)&X[(size_t)row * DIM + d4 * 4];
        *(float4*)&out[(size_t)row * DIM + d4 * 4] = q;
        float dx = q.x - x.x, dy = q.y - x.y, dz = q.z - x.z, dw = q.w - x.w;
        lsum += (double)(dx * dx) + (double)(dy * dy)
              + (double)(dz * dz) + (double)(dw * dw);
    }
    __shared__ double sred[256];
    sred[threadIdx.x] = lsum;
    __syncthreads();
    #pragma unroll
    for (int off = 128; off > 0; off >>= 1) {
        if (threadIdx.x < off) sred[threadIdx.x] += sred[threadIdx.x + off];
        __syncthreads();
    }
    if (threadIdx.x == 0) g_partial[blockIdx.x] = sred[0];
}

__global__ void finalize_kernel(float* __restrict__ out, int lossPos) {
    double s = 0.0;
    for (int i = 0; i < 512; i++) s += g_partial[i];
    float m = (float)(s / (double)((size_t)N_ROWS * DIM));
    out[lossPos] = m + 0.25f * m;     // q_latent + COMMITMENT_COST * e_latent
}

// ---------------------------------------------------------------------------
extern "C" void kernel_launch(void* const* d_in, const int* in_sizes, int n_in,
                              void* d_out, int out_size) {
    const float* X = (const float*)d_in[0];   // inputs  [64,512,256]
    const float* E = (const float*)d_in[1];   // embeddings [256,8192]
    float* out = (float*)d_out;

    enorm_kernel<<<KCODES / 256, 256>>>(E);
    transpose_kernel<<<dim3(KCODES / 32, DIM / 32), dim3(32, 8)>>>(E);
    xnorm_kernel<<<N_ROWS / 8, 256>>>(X);
    argmin_kernel<<<N_ROWS / 128, 256>>>(X, E);
    gather_loss_kernel<<<512, 256>>>(X, out);
    finalize_kernel<<<1, 1>>>(out, out_size - 1);
}

// round 5
// speedup vs baseline: 5.7933x; 5.7933x over previous
#include <cuda_runtime.h>
#include <cuda_bf16.h>
#include <math.h>
#include <stdint.h>

#define N_ROWS 32768
#define DIM    256
#define KCODES 8192

#define BM      128
#define BN      128
#define NTILES  (KCODES / BN)       // 64
#define CAND_MAX 32
#define MARGIN  0.125f

// ---- scratch (device globals; no runtime allocation) ----
__device__ float  g_xnorm[N_ROWS];
__device__ float  g_enorm[KCODES];
__device__ int    g_bestIdx[N_ROWS];
__device__ float  g_embT[KCODES * DIM];                 // [K][D] fp32 for gather/rescore
__device__ __nv_bfloat16 g_Eh[KCODES * DIM];            // [K][D] bf16
__device__ __nv_bfloat16 g_Xh[(size_t)N_ROWS * DIM];    // [N][D] bf16
__device__ int    g_cand[(size_t)N_ROWS * CAND_MAX];
__device__ int    g_candCnt[N_ROWS];
__device__ double g_partial[512];

// =========================== helpers ===================================
__device__ __forceinline__ uint32_t s2u(const void* p) {
    uint32_t a;
    asm("{ .reg .u64 t; cvta.to.shared.u64 t, %1; cvt.u32.u64 %0, t; }" : "=r"(a) : "l"(p));
    return a;
}
// order-preserving float->uint key (ascending float -> ascending uint)
__device__ __forceinline__ unsigned fenc(float f) {
    unsigned b = __float_as_uint(f);
    return (b & 0x80000000u) ? ~b : (b | 0x80000000u);
}
__device__ __forceinline__ float fdec(unsigned u) {
    return (u & 0x80000000u) ? __uint_as_float(u & 0x7FFFFFFFu) : __uint_as_float(~u);
}
__device__ __forceinline__ void ldsm4(uint32_t* d, uint32_t addr) {
    asm volatile("ldmatrix.sync.aligned.m8n8.x4.shared.b16 {%0,%1,%2,%3}, [%4];"
        : "=r"(d[0]), "=r"(d[1]), "=r"(d[2]), "=r"(d[3]) : "r"(addr));
}
__device__ __forceinline__ void mma_bf16(float* c, const uint32_t* a, const uint32_t* b) {
    asm volatile("mma.sync.aligned.m16n8k16.row.col.f32.bf16.bf16.f32 "
        "{%0,%1,%2,%3}, {%4,%5,%6,%7}, {%8,%9}, {%0,%1,%2,%3};"
        : "+f"(c[0]), "+f"(c[1]), "+f"(c[2]), "+f"(c[3])
        : "r"(a[0]), "r"(a[1]), "r"(a[2]), "r"(a[3]), "r"(b[0]), "r"(b[1]));
}
__device__ __forceinline__ void cpa16(uint32_t dst, const void* src) {
    asm volatile("cp.async.cg.shared.global [%0], [%1], 16;" :: "r"(dst), "l"(src));
}
#define CP_COMMIT() asm volatile("cp.async.commit_group;" ::: "memory")
#define CP_WAIT0()  asm volatile("cp.async.wait_group 0;" ::: "memory")

// ======================= prep kernels ================================
__global__ void enorm_kernel(const float* __restrict__ E) {
    int k = blockIdx.x * blockDim.x + threadIdx.x;
    if (k >= KCODES) return;
    float s = 0.0f;
    #pragma unroll 8
    for (int d = 0; d < DIM; d++) { float v = E[d * KCODES + k]; s += v * v; }
    g_enorm[k] = s;
}

// E [D][K] -> embT fp32 [K][D] + Eh bf16 [K][D]
__global__ void transpose_kernel(const float* __restrict__ E) {
    __shared__ float tile[32][33];
    int kBase = blockIdx.x * 32, dBase = blockIdx.y * 32;
    int tx = threadIdx.x, ty = threadIdx.y;   // (32, 8)
    #pragma unroll
    for (int i = 0; i < 32; i += 8)
        tile[ty + i][tx] = E[(size_t)(dBase + ty + i) * KCODES + kBase + tx];
    __syncthreads();
    #pragma unroll
    for (int i = 0; i < 32; i += 8) {
        float v = tile[tx][ty + i];
        size_t o = (size_t)(kBase + ty + i) * DIM + dBase + tx;
        g_embT[o] = v;
        g_Eh[o] = __float2bfloat16(v);
    }
}

__global__ void xnorm_kernel(const float* __restrict__ X) {
    int gwarp = (blockIdx.x * blockDim.x + threadIdx.x) >> 5;
    int lane = threadIdx.x & 31;
    if (gwarp >= N_ROWS) return;
    const float* xr = X + (size_t)gwarp * DIM;
    float s = 0.0f;
    #pragma unroll
    for (int i = 0; i < 2; i++) {
        float4 v = *(const float4*)&xr[lane * 8 + i * 4];
        s += v.x * v.x + v.y * v.y + v.z * v.z + v.w * v.w;
    }
    #pragma unroll
    for (int off = 16; off > 0; off >>= 1) s += __shfl_xor_sync(0xFFFFFFFFu, s, off);
    if (lane == 0) g_xnorm[gwarp] = s;
}

__global__ void convXh_kernel(const float* __restrict__ X) {
    int idx = blockIdx.x * 256 + threadIdx.x;   // N*32 threads, 8 elems each
    size_t base = (size_t)idx * 8;
    float4 a = *(const float4*)&X[base];
    float4 b = *(const float4*)&X[base + 4];
    __nv_bfloat162 p0 = make_bfloat162(__float2bfloat16(a.x), __float2bfloat16(a.y));
    __nv_bfloat162 p1 = make_bfloat162(__float2bfloat16(a.z), __float2bfloat16(a.w));
    __nv_bfloat162 p2 = make_bfloat162(__float2bfloat16(b.x), __float2bfloat16(b.y));
    __nv_bfloat162 p3 = make_bfloat162(__float2bfloat16(b.z), __float2bfloat16(b.w));
    uint4 v = make_uint4(*(uint32_t*)&p0, *(uint32_t*)&p1, *(uint32_t*)&p2, *(uint32_t*)&p3);
    *(uint4*)&g_Xh[base] = v;
}

__global__ void zerocnt_kernel() {
    g_candCnt[blockIdx.x * 256 + threadIdx.x] = 0;
}

// ======================= phase 1: bf16 HMMA + candidate collection =========
// smem: A 64KB | B0 64KB | B1 64KB | rowMinKey[128] | rowCnt[128]
#define SMEM_A   0
#define SMEM_B   65536
#define SMEM_KEY 196608
#define SMEM_CNT 197120
#define SMEM_P1  197632

__global__ __launch_bounds__(512, 1) void phase1_kernel() {
    extern __shared__ char smem[];
    uint32_t sb = s2u(smem);
    unsigned* rowMinKey = (unsigned*)(smem + SMEM_KEY);
    int*      rowCnt    = (int*)(smem + SMEM_CNT);

    int tid = threadIdx.x, lane = tid & 31, wid = tid >> 5;
    int wm = wid >> 2, wn = wid & 3;            // 4x4 warp grid, warp tile 32x32
    int g = lane >> 2, q = lane & 3;
    int rowBase = blockIdx.x * BM;

    if (tid < BM) { rowMinKey[tid] = 0xFFFFFFFFu; rowCnt[tid] = 0; }

    // ldmatrix row/chunk lane constants
    int rA = wm * 32 + (lane & 7) + ((lane >> 3) & 1) * 8;
    int caBit = lane >> 4;
    int rB = wn * 32 + (lane & 7) + ((lane >> 4) & 1) * 8;
    int cbBit = (lane >> 3) & 1;
    uint32_t aRowBase = sb + SMEM_A + rA * 512;

    // ---- initial loads: A tile (resident) + B tile 0 ----
    {
        const char* srcA = (const char*)g_Xh + (size_t)rowBase * 512;
        #pragma unroll
        for (int i = 0; i < 8; i++) {
            int lin = tid + i * 512;
            int r = lin >> 5, c = lin & 31;
            int gs = (c & ~7) | ((c ^ r) & 7);
            cpa16(sb + SMEM_A + r * 512 + gs * 16, srcA + (size_t)r * 512 + c * 16);
        }
        const char* srcB = (const char*)g_Eh;
        #pragma unroll
        for (int i = 0; i < 8; i++) {
            int lin = tid + i * 512;
            int r = lin >> 5, c = lin & 31;
            int gs = (c & ~7) | ((c ^ r) & 7);
            cpa16(sb + SMEM_B + r * 512 + gs * 16, srcB + (size_t)r * 512 + c * 16);
        }
        CP_COMMIT();
        CP_WAIT0();
    }
    __syncthreads();

    int buf = 0;
    for (int kt = 0; kt < NTILES; kt++) {
        // prefetch next B tile
        if (kt + 1 < NTILES) {
            const char* srcB = (const char*)g_Eh + (size_t)(kt + 1) * BN * 512;
            uint32_t dstB = sb + SMEM_B + (buf ^ 1) * 65536;
            #pragma unroll
            for (int i = 0; i < 8; i++) {
                int lin = tid + i * 512;
                int r = lin >> 5, c = lin & 31;
                int gs = (c & ~7) | ((c ^ r) & 7);
                cpa16(dstB + r * 512 + gs * 16, srcB + (size_t)r * 512 + c * 16);
            }
            CP_COMMIT();
        }

        // ---- MMA mainloop over D=256 (16 ksteps) ----
        float acc[2][4][4];
        #pragma unroll
        for (int mt = 0; mt < 2; mt++)
            #pragma unroll
            for (int nt = 0; nt < 4; nt++)
                #pragma unroll
                for (int e = 0; e < 4; e++) acc[mt][nt][e] = 0.0f;

        uint32_t bRowBase = sb + SMEM_B + buf * 65536 + rB * 512;
        #pragma unroll
        for (int ks = 0; ks < 16; ks++) {
            uint32_t af0[4], af1[4], bfA[4], bfB[4];
            int cA = ks * 2 + caBit;
            int gsA = (cA & ~7) | ((cA ^ rA) & 7);
            uint32_t aAddr = aRowBase + gsA * 16;
            ldsm4(af0, aAddr);
            ldsm4(af1, aAddr + 16 * 512);
            int cB = ks * 2 + cbBit;
            int gsB = (cB & ~7) | ((cB ^ rB) & 7);
            uint32_t bAddr = bRowBase + gsB * 16;
            ldsm4(bfA, bAddr);
            ldsm4(bfB, bAddr + 16 * 512);
            mma_bf16(acc[0][0], af0, bfA + 0);
            mma_bf16(acc[0][1], af0, bfA + 2);
            mma_bf16(acc[0][2], af0, bfB + 0);
            mma_bf16(acc[0][3], af0, bfB + 2);
            mma_bf16(acc[1][0], af1, bfA + 0);
            mma_bf16(acc[1][1], af1, bfA + 2);
            mma_bf16(acc[1][2], af1, bfB + 0);
            mma_bf16(acc[1][3], af1, bfB + 2);
        }

        // ---- epilogue: dist' = en - 2*dot, running min + candidate collect ----
        int kbase = kt * BN;
        float en[4][2];
        #pragma unroll
        for (int nt = 0; nt < 4; nt++)
            #pragma unroll
            for (int e = 0; e < 2; e++)
                en[nt][e] = __ldg(&g_enorm[kbase + wn * 32 + nt * 8 + q * 2 + e]);

        float dist[2][4][4];
        float lm[2][2];
        #pragma unroll
        for (int mt = 0; mt < 2; mt++) {
            lm[mt][0] = INFINITY; lm[mt][1] = INFINITY;
            #pragma unroll
            for (int nt = 0; nt < 4; nt++)
                #pragma unroll
                for (int h = 0; h < 2; h++)
                    #pragma unroll
                    for (int e = 0; e < 2; e++) {
                        float d = fmaf(-2.0f, acc[mt][nt][h * 2 + e], en[nt][e]);
                        dist[mt][nt][h * 2 + e] = d;
                        lm[mt][h] = fminf(lm[mt][h], d);
                    }
        }
        #pragma unroll
        for (int mt = 0; mt < 2; mt++)
            #pragma unroll
            for (int h = 0; h < 2; h++) {
                float v = lm[mt][h];
                v = fminf(v, __shfl_xor_sync(0xFFFFFFFFu, v, 1));
                v = fminf(v, __shfl_xor_sync(0xFFFFFFFFu, v, 2));
                lm[mt][h] = v;
            }
        if (q == 0) {
            #pragma unroll
            for (int mt = 0; mt < 2; mt++)
                #pragma unroll
                for (int h = 0; h < 2; h++)
                    atomicMin(&rowMinKey[wm * 32 + mt * 16 + g + h * 8], fenc(lm[mt][h]));
        }
        __syncthreads();

        #pragma unroll
        for (int mt = 0; mt < 2; mt++)
            #pragma unroll
            for (int h = 0; h < 2; h++) {
                int rl = wm * 32 + mt * 16 + g + h * 8;
                float thr = fdec(rowMinKey[rl]) + MARGIN;
                #pragma unroll
                for (int nt = 0; nt < 4; nt++)
                    #pragma unroll
                    for (int e = 0; e < 2; e++) {
                        if (dist[mt][nt][h * 2 + e] < thr) {
                            int pos = atomicAdd(&rowCnt[rl], 1);
                            if (pos < CAND_MAX)
                                g_cand[(size_t)(rowBase + rl) * CAND_MAX + pos] =
                                    kbase + wn * 32 + nt * 8 + q * 2 + e;
                        }
                    }
            }

        CP_WAIT0();
        __syncthreads();   // protects B buffer swap AND orders collect before next atomicMin
        buf ^= 1;
    }

    if (tid < BM) g_candCnt[rowBase + tid] = rowCnt[tid];
}

// ======================= phase 2: exact fp32 rescore =======================
__global__ __launch_bounds__(256) void rescore_kernel(const float* __restrict__ X) {
    int gw = (blockIdx.x * blockDim.x + threadIdx.x) >> 5;
    int lane = threadIdx.x & 31;
    const float* xr = X + (size_t)gw * DIM;
    float xn = g_xnorm[gw];
    int cnt = g_candCnt[gw];
    float bv = INFINITY;
    int   bi = 0x7FFFFFFF;

    if (cnt <= CAND_MAX) {
        float4 xa = *(const float4*)&xr[lane * 8];
        float4 xb = *(const float4*)&xr[lane * 8 + 4];
        for (int ci = 0; ci < cnt; ci++) {
            int k = g_cand[(size_t)gw * CAND_MAX + ci];
            const float* er = g_embT + (size_t)k * DIM;
            float4 ea = *(const float4*)&er[lane * 8];
            float4 eb = *(const float4*)&er[lane * 8 + 4];
            float d = xa.x * ea.x + xa.y * ea.y + xa.z * ea.z + xa.w * ea.w
                    + xb.x * eb.x + xb.y * eb.y + xb.z * eb.z + xb.w * eb.w;
            #pragma unroll
            for (int off = 16; off > 0; off >>= 1) d += __shfl_xor_sync(0xFFFFFFFFu, d, off);
            float dist = fmaf(-2.0f, d, xn) + g_enorm[k];
            if (dist < bv || (dist == bv && k < bi)) { bv = dist; bi = k; }
        }
    } else {
        // rare overflow: full exact scan (each lane handles k = lane + 32*i, ascending)
        for (int k = lane; k < KCODES; k += 32) {
            const float* er = g_embT + (size_t)k * DIM;
            float d = 0.0f;
            #pragma unroll 8
            for (int j = 0; j < DIM; j += 4) {
                float4 e4 = *(const float4*)&er[j];
                float4 x4 = *(const float4*)&xr[j];
                d += x4.x * e4.x + x4.y * e4.y + x4.z * e4.z + x4.w * e4.w;
            }
            float dist = fmaf(-2.0f, d, xn) + g_enorm[k];
            if (dist < bv || (dist == bv && k < bi)) { bv = dist; bi = k; }
        }
    }
    // lex-min (value, index) warp reduce — no-op for the uniform path
    #pragma unroll
    for (int off = 16; off > 0; off >>= 1) {
        float ov = __shfl_xor_sync(0xFFFFFFFFu, bv, off);
        int   oi = __shfl_xor_sync(0xFFFFFFFFu, bi, off);
        if (ov < bv || (ov == bv && oi < bi)) { bv = ov; bi = oi; }
    }
    if (lane == 0) g_bestIdx[gw] = bi;
}

// ======================= gather + loss =====================================
__global__ __launch_bounds__(256) void gather_loss_kernel(const float* __restrict__ X,
                                                          float* __restrict__ out) {
    int base = blockIdx.x * 64;
    double lsum = 0.0;
    for (int e = threadIdx.x; e < 64 * 64; e += 256) {
        int r = e >> 6, d4 = e & 63;
        int row = base + r;
        int idx = g_bestIdx[row];
        float4 qv = *(const float4*)&g_embT[(size_t)idx * DIM + d4 * 4];
        float4 xv = *(const float4*)&X[(size_t)row * DIM + d4 * 4];
        *(float4*)&out[(size_t)row * DIM + d4 * 4] = qv;
        float dx = qv.x - xv.x, dy = qv.y - xv.y, dz = qv.z - xv.z, dw = qv.w - xv.w;
        lsum += (double)(dx * dx) + (double)(dy * dy) + (double)(dz * dz) + (double)(dw * dw);
    }
    __shared__ double sred[256];
    sred[threadIdx.x] = lsum;
    __syncthreads();
    #pragma unroll
    for (int off = 128; off > 0; off >>= 1) {
        if (threadIdx.x < off) sred[threadIdx.x] += sred[threadIdx.x + off];
        __syncthreads();
    }
    if (threadIdx.x == 0) g_partial[blockIdx.x] = sred[0];
}

__global__ void finalize_kernel(float* __restrict__ out, int lossPos) {
    double s = 0.0;
    for (int i = 0; i < 512; i++) s += g_partial[i];
    float m = (float)(s / (double)((size_t)N_ROWS * DIM));
    out[lossPos] = m + 0.25f * m;
}

// ===========================================================================
extern "C" void kernel_launch(void* const* d_in, const int* in_sizes, int n_in,
                              void* d_out, int out_size) {
    const float* X = (const float*)d_in[0];   // inputs   [64,512,256]
    const float* E = (const float*)d_in[1];   // embeddings [256,8192]
    float* out = (float*)d_out;

    cudaFuncSetAttribute(phase1_kernel,
                         cudaFuncAttributeMaxDynamicSharedMemorySize, SMEM_P1);

    enorm_kernel<<<KCODES / 256, 256>>>(E);
    transpose_kernel<<<dim3(KCODES / 32, DIM / 32), dim3(32, 8)>>>(E);
    xnorm_kernel<<<N_ROWS / 8, 256>>>(X);
    convXh_kernel<<<(N_ROWS * 32) / 256, 256>>>(X);
    zerocnt_kernel<<<N_ROWS / 256, 256>>>();
    phase1_kernel<<<N_ROWS / BM, 512, SMEM_P1>>>();
    rescore_kernel<<<N_ROWS / 8, 256>>>(X);
    gather_loss_kernel<<<512, 256>>>(X, out);
    finalize_kernel<<<1, 1>>>(out, out_size - 1);
}